// round 9
// baseline (speedup 1.0000x reference)
#include <cuda_runtime.h>
#include <cuda_fp16.h>
#include <cstdint>
#include <math.h>

#define B_  8
#define T_  4096
#define W_  1024
#define H_  8
#define NCH 8      // chunks per batch (512 steps each)

// ---------------- scratch ----------------
__device__ __half g_Ph[(size_t)B_ * T_ * W_];          // chunk prefix products (fp16)
__device__ float  g_cinH[B_ * NCH * H_ * 128];         // inclusive carry h
__device__ float  g_cinP[B_ * NCH * H_ * 128];         // inclusive carry P
__device__ int    g_flag[B_ * NCH * H_];               // publish flags (zero-init)
__device__ unsigned char g_Wimg[(size_t)H_ * 2 * 32768]; // per head: w1,w2 fp16 (swizzled)

// ---------------- smem layout (bytes) ----------------
#define SP        130
#define SM_W      0                         // 2 x 32768 (fp16 w1,w2)
#define SM_XH     65536
#define SM_XL     81920
#define SM_SA     98304                     // 64*130*4 = 33280
#define SM_SNX    131584
#define SM_SC     164864
#define SM_B1     165376
#define SM_B2     165888
#define SM_SEGA   166400                    // 8*128*4
#define SM_SEGH   170496
#define SM_HRUN   174592                    // 2*128*4 parity
#define SM_PRUN   175616
#define SM_CV     176640                    // 128 floats carry bcast
#define SM_TOTAL  177152

__device__ __forceinline__ uint32_t smem_u32(const void* p) {
    uint32_t a;
    asm("{ .reg .u64 t; cvta.to.shared.u64 t, %1; cvt.u32.u64 %0, t; }" : "=r"(a) : "l"(p));
    return a;
}
__device__ __forceinline__ uint32_t swz(uint32_t o) {
    return o ^ (((o >> 8) & 7u) << 4);
}
__device__ __forceinline__ void ldm_x4(uint32_t* r, uint32_t addr) {
    asm volatile("ldmatrix.sync.aligned.m8n8.x4.shared.b16 {%0,%1,%2,%3}, [%4];"
        : "=r"(r[0]), "=r"(r[1]), "=r"(r[2]), "=r"(r[3]) : "r"(addr));
}
__device__ __forceinline__ void ldm_x4_t(uint32_t* r, uint32_t addr) {
    asm volatile("ldmatrix.sync.aligned.m8n8.x4.trans.shared.b16 {%0,%1,%2,%3}, [%4];"
        : "=r"(r[0]), "=r"(r[1]), "=r"(r[2]), "=r"(r[3]) : "r"(addr));
}
__device__ __forceinline__ void mma_f16(float* c, const uint32_t* a, const uint32_t* b) {
    asm volatile("mma.sync.aligned.m16n8k16.row.col.f32.f16.f16.f32 "
        "{%0,%1,%2,%3}, {%4,%5,%6,%7}, {%8,%9}, {%0,%1,%2,%3};"
        : "+f"(c[0]), "+f"(c[1]), "+f"(c[2]), "+f"(c[3])
        : "r"(a[0]), "r"(a[1]), "r"(a[2]), "r"(a[3]), "r"(b[0]), "r"(b[1]));
}
__device__ __forceinline__ float sigm(float v) {
    float t;
    asm("tanh.approx.f32 %0, %1;" : "=f"(t) : "f"(v * 0.5f));
    return fmaf(0.5f, t, 0.5f);
}
__device__ __forceinline__ float sqrt_ap(float v) {
    float r; asm("sqrt.approx.f32 %0, %1;" : "=f"(r) : "f"(v)); return r;
}
__device__ __forceinline__ uint32_t packh2(float a, float b) {
    __half2 t; t.x = __float2half_rn(a); t.y = __float2half_rn(b);
    return *(uint32_t*)&t;
}

// ---------------- kernel 0: weight prep (fp16, swizzled) ----------------
__global__ void __launch_bounds__(256) wprep_kernel(const float* __restrict__ w_in,
                                                    const float* __restrict__ w_a) {
    const int h = blockIdx.x;
    unsigned char* img = g_Wimg + (size_t)h * 65536;
    #pragma unroll
    for (int g = 0; g < 2; g++) {
        const float* wsrc = (g ? w_a : w_in) + h * 16384;
        unsigned char* WH = img + (size_t)g * 32768;
        for (int idx = threadIdx.x; idx < 4096; idx += 256) {
            int k = idx >> 5, n4 = (idx & 31) * 4;
            float4 v = *(const float4*)&wsrc[k * 128 + n4];
            uint32_t off = swz((uint32_t)k * 256u + (uint32_t)n4 * 2u);
            uint2 hp;
            hp.x = packh2(v.x, v.y); hp.y = packh2(v.z, v.w);
            *(uint2*)(WH + off) = hp;
        }
    }
}

// ---------------------------------------------------------------------------
// kernel 1: gates GEMM + chunk scan + decoupled-lookback carry + correction.
// block = (chunk, head). 512 threads.
// ---------------------------------------------------------------------------
__global__ void __launch_bounds__(512, 1) gates_kernel(
    const float* __restrict__ x, const float* __restrict__ b_in,
    const float* __restrict__ b_a, const float* __restrict__ a_param,
    float* __restrict__ y)
{
    extern __shared__ char sm[];
    const int tid = threadIdx.x, wid = tid >> 5, lane = tid & 31;
    const int h = blockIdx.y;
    const int bx = blockIdx.x;                // b*NCH + chunk
    const int c  = bx & (NCH - 1);
    const int row0 = bx * 512;

    float* scv  = (float*)(sm + SM_SC);
    float* b1v  = (float*)(sm + SM_B1);
    float* b2v  = (float*)(sm + SM_B2);
    float* sA   = (float*)(sm + SM_SA);
    float* sNX  = (float*)(sm + SM_SNX);
    float* sgA  = (float*)(sm + SM_SEGA);
    float* sgH  = (float*)(sm + SM_SEGH);
    float* hrun = (float*)(sm + SM_HRUN);
    float* prun = (float*)(sm + SM_PRUN);
    float* cvec = (float*)(sm + SM_CV);

    {
        const float4* src = (const float4*)(g_Wimg + (size_t)h * 65536);
        float4* dst = (float4*)(sm + SM_W);
        #pragma unroll 8
        for (int i = tid; i < 4096; i += 512) dst[i] = src[i];
    }
    if (tid < 128) {
        int ch = h * 128 + tid;
        scv[tid] = 8.f * log1pf(expf(a_param[ch]));
        b1v[tid] = b_in[ch];
        b2v[tid] = b_a[ch];
    }
    if (tid < 64) {
        float2 z; z.x = 0.f; z.y = 0.f;
        float2 o; o.x = 1.f; o.y = 1.f;
        *(float2*)&hrun[tid * 2] = z;
        *(float2*)&prun[tid * 2] = o;
    }

    const int pr = tid >> 5, pc4 = (tid & 31) * 4;
    float4 xr[4];
    #pragma unroll
    for (int i = 0; i < 4; i++)
        xr[i] = *(const float4*)&x[(size_t)(row0 + pr + i * 16) * W_ + h * 128 + pc4];
    __syncthreads();

    const uint32_t xh_b  = smem_u32(sm + SM_XH);
    const uint32_t wbase = smem_u32(sm + SM_W);

    const int cw = wid >> 2, rw = wid & 3;
    const int mrow = rw * 16, ncol = cw * 32;
    const int cp  = (tid & 63) * 2;
    const int seg = tid >> 6;

    for (int it = 0; it < 8; it++) {
        const int p = it & 1;
        // ---- stage x -> smem fp16 hi + residual ----
        #pragma unroll
        for (int i = 0; i < 4; i++) {
            float4 v = xr[i];
            uint32_t off = swz((uint32_t)(pr + i * 16) * 256u + (uint32_t)pc4 * 2u);
            uint2 hp, lp;
            hp.x = packh2(v.x, v.y); hp.y = packh2(v.z, v.w);
            __half2 h0 = *(__half2*)&hp.x;
            __half2 h1 = *(__half2*)&hp.y;
            lp.x = packh2(v.x - __half2float(h0.x), v.y - __half2float(h0.y));
            lp.y = packh2(v.z - __half2float(h1.x), v.w - __half2float(h1.y));
            *(uint2*)(sm + SM_XH + off) = hp;
            *(uint2*)(sm + SM_XL + off) = lp;
        }
        __syncthreads();

        if (it < 7) {
            #pragma unroll
            for (int i = 0; i < 4; i++)
                xr[i] = *(const float4*)&x[(size_t)(row0 + (it + 1) * 64 + pr + i * 16) * W_ + h * 128 + pc4];
        }

        // ---- mma ----
        float C[2][4][4];
        #pragma unroll
        for (int g = 0; g < 2; g++)
            #pragma unroll
            for (int n = 0; n < 4; n++)
                #pragma unroll
                for (int e = 0; e < 4; e++) C[g][n][e] = 0.f;

        #pragma unroll
        for (int kt = 0; kt < 8; kt++) {
            const int k0 = kt * 16;
            uint32_t ah[4];
            {
                uint32_t off = swz((uint32_t)(mrow + (lane & 15)) * 256u
                                   + (uint32_t)(k0 + (lane >> 4) * 8) * 2u);
                ldm_x4(ah, xh_b + off);
            }
            #pragma unroll
            for (int g = 0; g < 2; g++) {
                uint32_t bh[2][4];
                #pragma unroll
                for (int nn = 0; nn < 2; nn++) {
                    uint32_t off = swz((uint32_t)(k0 + (lane & 15)) * 256u
                                       + (uint32_t)(ncol + nn * 16 + (lane >> 4) * 8) * 2u);
                    ldm_x4_t(bh[nn], wbase + g * 32768 + off);
                }
                #pragma unroll
                for (int n = 0; n < 4; n++)
                    mma_f16(C[g][n], ah, &bh[n >> 1][(n & 1) * 2]);
            }
        }

        // ---- epilogue ----
        #pragma unroll
        for (int half = 0; half < 2; half++) {
            const int rloc = mrow + (lane >> 2) + half * 8;
            const bool rst = (((row0 + it * 64 + rloc) & (T_ - 1)) == 0);
            #pragma unroll
            for (int n = 0; n < 4; n++) {
                const int col = ncol + n * 8 + (lane & 3) * 2;
                float v1a = C[0][n][half * 2], v1b = C[0][n][half * 2 + 1];
                float v2a = C[1][n][half * 2], v2b = C[1][n][half * 2 + 1];
                uint32_t xoff = swz((uint32_t)rloc * 256u + (uint32_t)col * 2u);
                __half2 xhp = *(__half2*)(sm + SM_XH + xoff);
                __half2 xlp = *(__half2*)(sm + SM_XL + xoff);
                float x0 = __half2float(xhp.x) + __half2float(xlp.x);
                float x1 = __half2float(xhp.y) + __half2float(xlp.y);
                float gx0 = sigm(v1a + b1v[col]),     gx1 = sigm(v1b + b1v[col + 1]);
                float ga0 = sigm(v2a + b2v[col]),     ga1 = sigm(v2b + b2v[col + 1]);
                float a0 = __expf(-scv[col] * ga0);
                float a1 = __expf(-scv[col + 1] * ga1);
                float m0 = sqrt_ap(fmaxf(0.f, 1.f - a0 * a0));
                float m1 = sqrt_ap(fmaxf(0.f, 1.f - a1 * a1));
                if (rst) { a0 = 0.f; a1 = 0.f; m0 = 1.f; m1 = 1.f; }
                float2 av; av.x = a0; av.y = a1;
                float2 nv; nv.x = x0 * gx0 * m0; nv.y = x1 * gx1 * m1;
                *(float2*)&sA [rloc * SP + col] = av;
                *(float2*)&sNX[rloc * SP + col] = nv;
            }
        }
        __syncthreads();

        // ---- phase 1: 8-step register scan, publish seg summaries ----
        float2 yl[8], pl[8];
        float2 hv; hv.x = 0.f; hv.y = 0.f;
        float2 pv; pv.x = 1.f; pv.y = 1.f;
        const int t0 = seg * 8;
        #pragma unroll
        for (int t = 0; t < 8; t++) {
            float2 a  = *(float2*)&sA [(t0 + t) * SP + cp];
            float2 nx = *(float2*)&sNX[(t0 + t) * SP + cp];
            hv.x = fmaf(a.x, hv.x, nx.x); hv.y = fmaf(a.y, hv.y, nx.y);
            pv.x *= a.x;                  pv.y *= a.y;
            yl[t] = hv; pl[t] = pv;
        }
        *(float2*)&sgA[seg * 128 + cp] = pv;
        *(float2*)&sgH[seg * 128 + cp] = hv;
        __syncthreads();

        // ---- phase 2+3: fold carry, store y_local (+P fp16 if c>0) ----
        float2 cih = *(float2*)&hrun[p * 128 + cp];
        float2 cip = *(float2*)&prun[p * 128 + cp];
        for (int s = 0; s < seg; s++) {
            float2 A  = *(float2*)&sgA[s * 128 + cp];
            float2 Hh = *(float2*)&sgH[s * 128 + cp];
            cih.x = fmaf(A.x, cih.x, Hh.x); cih.y = fmaf(A.y, cih.y, Hh.y);
            cip.x *= A.x;                   cip.y *= A.y;
        }
        if (seg == 7) {
            float2 nh, np;
            nh.x = fmaf(pv.x, cih.x, hv.x); nh.y = fmaf(pv.y, cih.y, hv.y);
            np.x = cip.x * pv.x;            np.y = cip.y * pv.y;
            *(float2*)&hrun[(p ^ 1) * 128 + cp] = nh;
            *(float2*)&prun[(p ^ 1) * 128 + cp] = np;
        }
        {
            const size_t gtile = (size_t)(row0 + it * 64 + t0) * W_ + h * 128 + cp;
            #pragma unroll
            for (int t = 0; t < 8; t++) {
                float2 yv;
                yv.x = fmaf(pl[t].x, cih.x, yl[t].x);
                yv.y = fmaf(pl[t].y, cih.y, yl[t].y);
                *(float2*)&y[gtile + (size_t)t * W_] = yv;
                if (c != 0) {
                    __half2 Pv;
                    Pv.x = __float2half_rn(pl[t].x * cip.x);
                    Pv.y = __float2half_rn(pl[t].y * cip.y);
                    *(__half2*)&g_Ph[gtile + (size_t)t * W_] = Pv;
                }
            }
        }
    }
    __syncthreads();   // totals valid in parity-0 hrun/prun

    // ---- decoupled lookback: consume predecessor carry, publish inclusive ----
    if (c != 0) {
        if (tid == 0) {
            while (atomicAdd(&g_flag[(bx - 1) * H_ + h], 0) == 0) { __nanosleep(100); }
        }
        __syncthreads();
        __threadfence();
        if (tid < 128) {
            int pidx = ((bx - 1) * H_ + h) * 128 + tid;
            float hp = g_cinH[pidx];
            float Pp = g_cinP[pidx];
            cvec[tid] = hp;
            int oidx = (bx * H_ + h) * 128 + tid;
            g_cinH[oidx] = fmaf(prun[tid], hp, hrun[tid]);
            g_cinP[oidx] = Pp * prun[tid];
        }
    } else {
        if (tid < 128) {
            int oidx = (bx * H_ + h) * 128 + tid;
            g_cinH[oidx] = hrun[tid];
            g_cinP[oidx] = prun[tid];
        }
    }
    __threadfence();
    __syncthreads();
    if (tid == 0) atomicExch(&g_flag[bx * H_ + h], 1);

    // ---- correction pass: y += P * h_prev (L2-resident re-read) ----
    if (c != 0) {
        const float hp = cvec[tid & 127];
        const size_t base = (size_t)row0 * W_ + h * 128 + (tid & 127);
        #pragma unroll 8
        for (int t = tid >> 7; t < 512; t += 4) {
            size_t idx = base + (size_t)t * W_;
            float Pv = __half2float(g_Ph[idx]);
            y[idx] = fmaf(Pv, hp, y[idx]);
        }
    }
}

// ---------------------------------------------------------------------------
extern "C" void kernel_launch(void* const* d_in, const int* in_sizes, int n_in,
                              void* d_out, int out_size)
{
    const float* x       = (const float*)d_in[0];
    const float* w_in    = (const float*)d_in[1];
    const float* b_in    = (const float*)d_in[2];
    const float* w_a     = (const float*)d_in[3];
    const float* b_a     = (const float*)d_in[4];
    const float* a_param = (const float*)d_in[5];
    float* y = (float*)d_out;

    cudaFuncSetAttribute(gates_kernel,
                         cudaFuncAttributeMaxDynamicSharedMemorySize, SM_TOTAL);

    wprep_kernel<<<H_, 256>>>(w_in, w_a);
    gates_kernel<<<dim3(B_ * NCH, H_), 512, SM_TOTAL>>>(x, b_in, b_a, a_param, y);
}

// round 10
// speedup vs baseline: 1.3738x; 1.3738x over previous
#include <cuda_runtime.h>
#include <cuda_fp16.h>
#include <cstdint>
#include <math.h>

#define B_  8
#define T_  4096
#define W_  1024
#define H_  8
#define NCH 8      // chunks per batch (512 steps each)

// ---------------- scratch ----------------
__device__ __half g_Ph[(size_t)B_ * T_ * W_];          // chunk prefix products (fp16)
__device__ float  g_Aprod[B_ * NCH * W_];
__device__ float  g_hlast[B_ * NCH * W_];
__device__ unsigned char g_Wimg[(size_t)H_ * 2 * 32768]; // per head: w1,w2 fp16 (swizzled)

// ---------------- smem layout (bytes) ----------------
#define SP        130
#define SM_W      0                         // 2 x 32768 (fp16 w1,w2)
#define SM_XH     65536                     // 16384
#define SM_SA     81920                     // 64*130*4 = 33280
#define SM_SNX    115200                    // 33280
#define SM_SC     148480
#define SM_B1     148992
#define SM_B2     149504
#define SM_SEGA   150016                    // 8*128*4
#define SM_SEGH   154112
#define SM_HRUN   158208                    // 2*128*4 parity
#define SM_PRUN   159232
#define SM_TOTAL  160256

__device__ __forceinline__ uint32_t smem_u32(const void* p) {
    uint32_t a;
    asm("{ .reg .u64 t; cvta.to.shared.u64 t, %1; cvt.u32.u64 %0, t; }" : "=r"(a) : "l"(p));
    return a;
}
__device__ __forceinline__ uint32_t swz(uint32_t o) {
    return o ^ (((o >> 8) & 7u) << 4);
}
__device__ __forceinline__ void ldm_x4(uint32_t* r, uint32_t addr) {
    asm volatile("ldmatrix.sync.aligned.m8n8.x4.shared.b16 {%0,%1,%2,%3}, [%4];"
        : "=r"(r[0]), "=r"(r[1]), "=r"(r[2]), "=r"(r[3]) : "r"(addr));
}
__device__ __forceinline__ void ldm_x4_t(uint32_t* r, uint32_t addr) {
    asm volatile("ldmatrix.sync.aligned.m8n8.x4.trans.shared.b16 {%0,%1,%2,%3}, [%4];"
        : "=r"(r[0]), "=r"(r[1]), "=r"(r[2]), "=r"(r[3]) : "r"(addr));
}
__device__ __forceinline__ void mma_f16(float* c, const uint32_t* a, const uint32_t* b) {
    asm volatile("mma.sync.aligned.m16n8k16.row.col.f32.f16.f16.f32 "
        "{%0,%1,%2,%3}, {%4,%5,%6,%7}, {%8,%9}, {%0,%1,%2,%3};"
        : "+f"(c[0]), "+f"(c[1]), "+f"(c[2]), "+f"(c[3])
        : "r"(a[0]), "r"(a[1]), "r"(a[2]), "r"(a[3]), "r"(b[0]), "r"(b[1]));
}
__device__ __forceinline__ float sigm(float v) {
    float t;
    asm("tanh.approx.f32 %0, %1;" : "=f"(t) : "f"(v * 0.5f));
    return fmaf(0.5f, t, 0.5f);
}
__device__ __forceinline__ float sqrt_ap(float v) {
    float r; asm("sqrt.approx.f32 %0, %1;" : "=f"(r) : "f"(v)); return r;
}
__device__ __forceinline__ uint32_t packh2(float a, float b) {
    __half2 t; t.x = __float2half_rn(a); t.y = __float2half_rn(b);
    return *(uint32_t*)&t;
}

// ---------------- kernel 0: weight prep (fp16, swizzled) ----------------
__global__ void __launch_bounds__(256) wprep_kernel(const float* __restrict__ w_in,
                                                    const float* __restrict__ w_a) {
    const int h = blockIdx.x;
    unsigned char* img = g_Wimg + (size_t)h * 65536;
    #pragma unroll
    for (int g = 0; g < 2; g++) {
        const float* wsrc = (g ? w_a : w_in) + h * 16384;
        unsigned char* WH = img + (size_t)g * 32768;
        for (int idx = threadIdx.x; idx < 4096; idx += 256) {
            int k = idx >> 5, n4 = (idx & 31) * 4;
            float4 v = *(const float4*)&wsrc[k * 128 + n4];
            uint32_t off = swz((uint32_t)k * 256u + (uint32_t)n4 * 2u);
            uint2 hp;
            hp.x = packh2(v.x, v.y); hp.y = packh2(v.z, v.w);
            *(uint2*)(WH + off) = hp;
        }
    }
}

// ---------------------------------------------------------------------------
// kernel 1: gates GEMM + fused segmented chunk-local scan. 512 threads.
// ---------------------------------------------------------------------------
__global__ void __launch_bounds__(512, 1) gates_kernel(
    const float* __restrict__ x, const float* __restrict__ b_in,
    const float* __restrict__ b_a, const float* __restrict__ a_param,
    float* __restrict__ y)
{
    extern __shared__ char sm[];
    const int tid = threadIdx.x, wid = tid >> 5, lane = tid & 31;
    const int h = blockIdx.y;
    const int bx = blockIdx.x;                 // b*NCH + chunk
    const int c  = bx & (NCH - 1);
    const int row0 = bx * 512;

    float* scv  = (float*)(sm + SM_SC);
    float* b1v  = (float*)(sm + SM_B1);
    float* b2v  = (float*)(sm + SM_B2);
    float* sA   = (float*)(sm + SM_SA);
    float* sNX  = (float*)(sm + SM_SNX);
    float* sgA  = (float*)(sm + SM_SEGA);
    float* sgH  = (float*)(sm + SM_SEGH);
    float* hrun = (float*)(sm + SM_HRUN);
    float* prun = (float*)(sm + SM_PRUN);

    {
        const float4* src = (const float4*)(g_Wimg + (size_t)h * 65536);
        float4* dst = (float4*)(sm + SM_W);
        #pragma unroll 8
        for (int i = tid; i < 4096; i += 512) dst[i] = src[i];
    }
    if (tid < 128) {
        int ch = h * 128 + tid;
        scv[tid] = 8.f * log1pf(expf(a_param[ch]));
        b1v[tid] = b_in[ch];
        b2v[tid] = b_a[ch];
    }
    if (tid < 64) {
        float2 z; z.x = 0.f; z.y = 0.f;
        float2 o; o.x = 1.f; o.y = 1.f;
        *(float2*)&hrun[tid * 2] = z;
        *(float2*)&prun[tid * 2] = o;
    }

    const int pr = tid >> 5, pc4 = (tid & 31) * 4;
    float4 xr[4];
    #pragma unroll
    for (int i = 0; i < 4; i++)
        xr[i] = *(const float4*)&x[(size_t)(row0 + pr + i * 16) * W_ + h * 128 + pc4];
    __syncthreads();

    const uint32_t xh_b  = smem_u32(sm + SM_XH);
    const uint32_t wbase = smem_u32(sm + SM_W);

    const int cw = wid >> 2, rw = wid & 3;
    const int mrow = rw * 16, ncol = cw * 32;
    const int cp  = (tid & 63) * 2;
    const int seg = tid >> 6;

    for (int it = 0; it < 8; it++) {
        const int p = it & 1;
        // ---- stage x -> smem fp16 (swizzled) ----
        #pragma unroll
        for (int i = 0; i < 4; i++) {
            float4 v = xr[i];
            uint32_t off = swz((uint32_t)(pr + i * 16) * 256u + (uint32_t)pc4 * 2u);
            uint2 hp;
            hp.x = packh2(v.x, v.y); hp.y = packh2(v.z, v.w);
            *(uint2*)(sm + SM_XH + off) = hp;
        }
        __syncthreads();

        if (it < 7) {
            #pragma unroll
            for (int i = 0; i < 4; i++)
                xr[i] = *(const float4*)&x[(size_t)(row0 + (it + 1) * 64 + pr + i * 16) * W_ + h * 128 + pc4];
        }

        // ---- mma: single-pass fp16, both gemms ----
        float C[2][4][4];
        #pragma unroll
        for (int g = 0; g < 2; g++)
            #pragma unroll
            for (int n = 0; n < 4; n++)
                #pragma unroll
                for (int e = 0; e < 4; e++) C[g][n][e] = 0.f;

        #pragma unroll
        for (int kt = 0; kt < 8; kt++) {
            const int k0 = kt * 16;
            uint32_t ah[4];
            {
                uint32_t off = swz((uint32_t)(mrow + (lane & 15)) * 256u
                                   + (uint32_t)(k0 + (lane >> 4) * 8) * 2u);
                ldm_x4(ah, xh_b + off);
            }
            #pragma unroll
            for (int g = 0; g < 2; g++) {
                uint32_t bh[2][4];
                #pragma unroll
                for (int nn = 0; nn < 2; nn++) {
                    uint32_t off = swz((uint32_t)(k0 + (lane & 15)) * 256u
                                       + (uint32_t)(ncol + nn * 16 + (lane >> 4) * 8) * 2u);
                    ldm_x4_t(bh[nn], wbase + g * 32768 + off);
                }
                #pragma unroll
                for (int n = 0; n < 4; n++)
                    mma_f16(C[g][n], ah, &bh[n >> 1][(n & 1) * 2]);
            }
        }

        // ---- epilogue: gates -> smem a/nx tiles ----
        #pragma unroll
        for (int half = 0; half < 2; half++) {
            const int rloc = mrow + (lane >> 2) + half * 8;
            const bool rst = (((row0 + it * 64 + rloc) & (T_ - 1)) == 0);
            #pragma unroll
            for (int n = 0; n < 4; n++) {
                const int col = ncol + n * 8 + (lane & 3) * 2;
                float v1a = C[0][n][half * 2], v1b = C[0][n][half * 2 + 1];
                float v2a = C[1][n][half * 2], v2b = C[1][n][half * 2 + 1];
                uint32_t xoff = swz((uint32_t)rloc * 256u + (uint32_t)col * 2u);
                __half2 xhp = *(__half2*)(sm + SM_XH + xoff);
                float x0 = __half2float(xhp.x);
                float x1 = __half2float(xhp.y);
                float gx0 = sigm(v1a + b1v[col]),     gx1 = sigm(v1b + b1v[col + 1]);
                float ga0 = sigm(v2a + b2v[col]),     ga1 = sigm(v2b + b2v[col + 1]);
                float a0 = __expf(-scv[col] * ga0);
                float a1 = __expf(-scv[col + 1] * ga1);
                float m0 = sqrt_ap(fmaxf(0.f, 1.f - a0 * a0));
                float m1 = sqrt_ap(fmaxf(0.f, 1.f - a1 * a1));
                if (rst) { a0 = 0.f; a1 = 0.f; m0 = 1.f; m1 = 1.f; }
                float2 av; av.x = a0; av.y = a1;
                float2 nv; nv.x = x0 * gx0 * m0; nv.y = x1 * gx1 * m1;
                *(float2*)&sA [rloc * SP + col] = av;
                *(float2*)&sNX[rloc * SP + col] = nv;
            }
        }
        __syncthreads();

        // ---- phase 1: 8-step register scan, publish seg summaries ----
        float2 yl[8], pl[8];
        float2 hv; hv.x = 0.f; hv.y = 0.f;
        float2 pv; pv.x = 1.f; pv.y = 1.f;
        const int t0 = seg * 8;
        #pragma unroll
        for (int t = 0; t < 8; t++) {
            float2 a  = *(float2*)&sA [(t0 + t) * SP + cp];
            float2 nx = *(float2*)&sNX[(t0 + t) * SP + cp];
            hv.x = fmaf(a.x, hv.x, nx.x); hv.y = fmaf(a.y, hv.y, nx.y);
            pv.x *= a.x;                  pv.y *= a.y;
            yl[t] = hv; pl[t] = pv;
        }
        *(float2*)&sgA[seg * 128 + cp] = pv;
        *(float2*)&sgH[seg * 128 + cp] = hv;
        __syncthreads();

        // ---- phase 2+3: fold inbound carry, fix + store to gmem ----
        float2 cih = *(float2*)&hrun[p * 128 + cp];
        float2 cip = *(float2*)&prun[p * 128 + cp];
        for (int s = 0; s < seg; s++) {
            float2 A  = *(float2*)&sgA[s * 128 + cp];
            float2 Hh = *(float2*)&sgH[s * 128 + cp];
            cih.x = fmaf(A.x, cih.x, Hh.x); cih.y = fmaf(A.y, cih.y, Hh.y);
            cip.x *= A.x;                   cip.y *= A.y;
        }
        if (seg == 7) {
            float2 nh, np;
            nh.x = fmaf(pv.x, cih.x, hv.x); nh.y = fmaf(pv.y, cih.y, hv.y);
            np.x = cip.x * pv.x;            np.y = cip.y * pv.y;
            *(float2*)&hrun[(p ^ 1) * 128 + cp] = nh;
            *(float2*)&prun[(p ^ 1) * 128 + cp] = np;
        }
        {
            const size_t gtile = (size_t)(row0 + it * 64 + t0) * W_ + h * 128 + cp;
            #pragma unroll
            for (int t = 0; t < 8; t++) {
                float2 yv;
                yv.x = fmaf(pl[t].x, cih.x, yl[t].x);
                yv.y = fmaf(pl[t].y, cih.y, yl[t].y);
                *(float2*)&y[gtile + (size_t)t * W_] = yv;
                if (c != 0) {
                    __half2 Pv;
                    Pv.x = __float2half_rn(pl[t].x * cip.x);
                    Pv.y = __float2half_rn(pl[t].y * cip.y);
                    *(__half2*)&g_Ph[gtile + (size_t)t * W_] = Pv;
                }
            }
        }
    }

    __syncthreads();
    if (tid < 64) {   // final carries live in parity 0 (after 8 iters)
        int sidx = bx * W_ + h * 128 + cp;
        *(float2*)&g_hlast[sidx] = *(float2*)&hrun[cp];
        *(float2*)&g_Aprod[sidx] = *(float2*)&prun[cp];
    }
}

// ---------------- kernel 2: apply carries (inline carry chain) ----------------
__global__ void __launch_bounds__(1024) apply_kernel(float* __restrict__ y)
{
    const int sub  = blockIdx.x & 7;
    const int c    = (blockIdx.x >> 3) + 1;     // 1..7
    const int b    = blockIdx.y;
    const int pid  = threadIdx.x & 511;         // channel pair
    const int rpar = threadIdx.x >> 9;          // row parity
    const int ch   = pid * 2;

    // inline cross-chunk carry: fold chunks 0..c-1
    float2 carry; carry.x = 0.f; carry.y = 0.f;
    for (int s = 0; s < c; s++) {
        int sidx = (b * NCH + s) * W_ + ch;
        float2 A  = *(const float2*)&g_Aprod[sidx];
        float2 Hh = *(const float2*)&g_hlast[sidx];
        carry.x = fmaf(A.x, carry.x, Hh.x);
        carry.y = fmaf(A.y, carry.y, Hh.y);
    }

    size_t base = ((size_t)b * T_ + (size_t)c * 512 + (size_t)sub * 64 + rpar) * W_ + ch;
    #pragma unroll 8
    for (int t = 0; t < 32; t++) {
        size_t idx = base + (size_t)t * 2 * W_;
        __half2 Ph = *(const __half2*)&g_Ph[idx];
        float2 yv = *(float2*)&y[idx];
        yv.x = fmaf(__half2float(Ph.x), carry.x, yv.x);
        yv.y = fmaf(__half2float(Ph.y), carry.y, yv.y);
        *(float2*)&y[idx] = yv;
    }
}

// ---------------------------------------------------------------------------
extern "C" void kernel_launch(void* const* d_in, const int* in_sizes, int n_in,
                              void* d_out, int out_size)
{
    const float* x       = (const float*)d_in[0];
    const float* w_in    = (const float*)d_in[1];
    const float* b_in    = (const float*)d_in[2];
    const float* w_a     = (const float*)d_in[3];
    const float* b_a     = (const float*)d_in[4];
    const float* a_param = (const float*)d_in[5];
    float* y = (float*)d_out;

    cudaFuncSetAttribute(gates_kernel,
                         cudaFuncAttributeMaxDynamicSharedMemorySize, SM_TOTAL);

    wprep_kernel<<<H_, 256>>>(w_in, w_a);
    gates_kernel<<<dim3(B_ * NCH, H_), 512, SM_TOTAL>>>(x, b_in, b_a, a_param, y);
    apply_kernel<<<dim3(56, B_), 1024>>>(y);
}

// round 11
// speedup vs baseline: 1.5303x; 1.1139x over previous
#include <cuda_runtime.h>
#include <cuda_fp16.h>
#include <cstdint>
#include <math.h>

#define B_  8
#define T_  4096
#define W_  1024
#define H_  8
#define NCH 8      // chunks per batch (512 steps each)

// ---------------- scratch ----------------
__device__ __half g_Ph[(size_t)B_ * T_ * W_];          // chunk prefix products (fp16)
__device__ float  g_Aprod[B_ * NCH * W_];
__device__ float  g_hlast[B_ * NCH * W_];
__device__ unsigned char g_Wimg[(size_t)H_ * 2 * 32768]; // per (head,half): w1,w2 fp16 16KB each

// ---------------- smem layout (bytes) ----------------
#define SP        66                        // scan tile row stride (floats)
#define SM_W      0                         // 2 x 16384 (fp16 w1,w2 half-cols)
#define SM_XH     32768                     // 16384 (64 rows x 128 k fp16)
#define SM_SA     49152                     // 64*66*4 = 16896
#define SM_SNX    66048                     // 16896
#define SM_SC     82944                     // 256
#define SM_B1     83200
#define SM_B2     83456
#define SM_SEGA   83712                     // 8*64*4 = 2048
#define SM_SEGH   85760
#define SM_HRUN   87808                     // 2*64*4 parity
#define SM_PRUN   88320
#define SM_TOTAL  88832

__device__ __forceinline__ uint32_t smem_u32(const void* p) {
    uint32_t a;
    asm("{ .reg .u64 t; cvta.to.shared.u64 t, %1; cvt.u32.u64 %0, t; }" : "=r"(a) : "l"(p));
    return a;
}
// swizzle for 256B rows (XH): XOR row bits [8:11) into 16B-unit bits [4:7)
__device__ __forceinline__ uint32_t swz256(uint32_t o) {
    return o ^ (((o >> 8) & 7u) << 4);
}
// swizzle for 128B rows (W tiles): standard SW128
__device__ __forceinline__ uint32_t swz128(uint32_t o) {
    return o ^ ((o >> 3) & 0x70u);
}
__device__ __forceinline__ void ldm_x4(uint32_t* r, uint32_t addr) {
    asm volatile("ldmatrix.sync.aligned.m8n8.x4.shared.b16 {%0,%1,%2,%3}, [%4];"
        : "=r"(r[0]), "=r"(r[1]), "=r"(r[2]), "=r"(r[3]) : "r"(addr));
}
__device__ __forceinline__ void ldm_x4_t(uint32_t* r, uint32_t addr) {
    asm volatile("ldmatrix.sync.aligned.m8n8.x4.trans.shared.b16 {%0,%1,%2,%3}, [%4];"
        : "=r"(r[0]), "=r"(r[1]), "=r"(r[2]), "=r"(r[3]) : "r"(addr));
}
__device__ __forceinline__ void mma_f16(float* c, const uint32_t* a, const uint32_t* b) {
    asm volatile("mma.sync.aligned.m16n8k16.row.col.f32.f16.f16.f32 "
        "{%0,%1,%2,%3}, {%4,%5,%6,%7}, {%8,%9}, {%0,%1,%2,%3};"
        : "+f"(c[0]), "+f"(c[1]), "+f"(c[2]), "+f"(c[3])
        : "r"(a[0]), "r"(a[1]), "r"(a[2]), "r"(a[3]), "r"(b[0]), "r"(b[1]));
}
__device__ __forceinline__ float sigm(float v) {
    float t;
    asm("tanh.approx.f32 %0, %1;" : "=f"(t) : "f"(v * 0.5f));
    return fmaf(0.5f, t, 0.5f);
}
__device__ __forceinline__ float sqrt_ap(float v) {
    float r; asm("sqrt.approx.f32 %0, %1;" : "=f"(r) : "f"(v)); return r;
}
__device__ __forceinline__ uint32_t packh2(float a, float b) {
    __half2 t; t.x = __float2half_rn(a); t.y = __float2half_rn(b);
    return *(uint32_t*)&t;
}

// ---------------- kernel 0: weight prep (fp16, half-col images) ----------------
__global__ void __launch_bounds__(256) wprep_kernel(const float* __restrict__ w_in,
                                                    const float* __restrict__ w_a) {
    const int h = blockIdx.x, half = blockIdx.y;
    unsigned char* img = g_Wimg + (size_t)(h * 2 + half) * 32768;
    #pragma unroll
    for (int g = 0; g < 2; g++) {
        const float* wsrc = (g ? w_a : w_in) + h * 16384 + half * 64;
        unsigned char* WH = img + (size_t)g * 16384;
        for (int idx = threadIdx.x; idx < 2048; idx += 256) {
            int k = idx >> 4, n4 = (idx & 15) * 4;
            float4 v = *(const float4*)&wsrc[k * 128 + n4];
            uint32_t off = swz128((uint32_t)k * 128u + (uint32_t)n4 * 2u);
            uint2 hp;
            hp.x = packh2(v.x, v.y); hp.y = packh2(v.z, v.w);
            *(uint2*)(WH + off) = hp;
        }
    }
}

// ---------------------------------------------------------------------------
// kernel 1: gates GEMM + fused scan. block = (chunk, head-half). 256 threads.
// 2 CTAs/SM (88.8 KB smem each).
// ---------------------------------------------------------------------------
__global__ void __launch_bounds__(256, 2) gates_kernel(
    const float* __restrict__ x, const float* __restrict__ b_in,
    const float* __restrict__ b_a, const float* __restrict__ a_param,
    float* __restrict__ y)
{
    extern __shared__ char sm[];
    const int tid = threadIdx.x, wid = tid >> 5, lane = tid & 31;
    const int h = blockIdx.y >> 1, half = blockIdx.y & 1;
    const int bx = blockIdx.x;                 // b*NCH + chunk
    const int c  = bx & (NCH - 1);
    const int row0 = bx * 512;
    const int col0 = h * 128 + half * 64;      // global channel base

    float* scv  = (float*)(sm + SM_SC);
    float* b1v  = (float*)(sm + SM_B1);
    float* b2v  = (float*)(sm + SM_B2);
    float* sA   = (float*)(sm + SM_SA);
    float* sNX  = (float*)(sm + SM_SNX);
    float* sgA  = (float*)(sm + SM_SEGA);
    float* sgH  = (float*)(sm + SM_SEGH);
    float* hrun = (float*)(sm + SM_HRUN);
    float* prun = (float*)(sm + SM_PRUN);

    {
        const float4* src = (const float4*)(g_Wimg + (size_t)(h * 2 + half) * 32768);
        float4* dst = (float4*)(sm + SM_W);
        #pragma unroll 8
        for (int i = tid; i < 2048; i += 256) dst[i] = src[i];
    }
    if (tid < 64) {
        int ch = col0 + tid;
        scv[tid] = 8.f * log1pf(expf(a_param[ch]));
        b1v[tid] = b_in[ch];
        b2v[tid] = b_a[ch];
    }
    if (tid < 32) {
        float2 z; z.x = 0.f; z.y = 0.f;
        float2 o; o.x = 1.f; o.y = 1.f;
        *(float2*)&hrun[tid * 2] = z;
        *(float2*)&prun[tid * 2] = o;
    }

    // x tile prefetch: 64 rows x 128 cols, 256 threads, 8 float4 each
    const int pr = tid >> 5, pc4 = (tid & 31) * 4;
    float4 xr[8];
    #pragma unroll
    for (int i = 0; i < 8; i++)
        xr[i] = *(const float4*)&x[(size_t)(row0 + pr + i * 8) * W_ + h * 128 + pc4];
    __syncthreads();

    const uint32_t xh_b  = smem_u32(sm + SM_XH);
    const uint32_t wbase = smem_u32(sm + SM_W);

    const int cw = wid >> 2, rw = wid & 3;     // warp tile: rows rw*16, cols cw*32
    const int mrow = rw * 16, ncol = cw * 32;
    const int cp  = lane * 2;                  // scan channel pair (local)
    const int seg = wid;                       // warp = scan segment

    for (int it = 0; it < 8; it++) {
        const int p = it & 1;
        // ---- stage x -> smem fp16 (swizzled 256B rows) ----
        #pragma unroll
        for (int i = 0; i < 8; i++) {
            float4 v = xr[i];
            uint32_t off = swz256((uint32_t)(pr + i * 8) * 256u + (uint32_t)pc4 * 2u);
            uint2 hp;
            hp.x = packh2(v.x, v.y); hp.y = packh2(v.z, v.w);
            *(uint2*)(sm + SM_XH + off) = hp;
        }
        __syncthreads();

        if (it < 7) {
            #pragma unroll
            for (int i = 0; i < 8; i++)
                xr[i] = *(const float4*)&x[(size_t)(row0 + (it + 1) * 64 + pr + i * 8) * W_ + h * 128 + pc4];
        }

        // ---- mma: single-pass fp16, both gemms, warp tile 16x32 ----
        float C[2][4][4];
        #pragma unroll
        for (int g = 0; g < 2; g++)
            #pragma unroll
            for (int n = 0; n < 4; n++)
                #pragma unroll
                for (int e = 0; e < 4; e++) C[g][n][e] = 0.f;

        #pragma unroll
        for (int kt = 0; kt < 8; kt++) {
            const int k0 = kt * 16;
            uint32_t ah[4];
            {
                uint32_t off = swz256((uint32_t)(mrow + (lane & 15)) * 256u
                                      + (uint32_t)(k0 + (lane >> 4) * 8) * 2u);
                ldm_x4(ah, xh_b + off);
            }
            #pragma unroll
            for (int g = 0; g < 2; g++) {
                uint32_t bh[2][4];
                #pragma unroll
                for (int nn = 0; nn < 2; nn++) {
                    uint32_t off = swz128((uint32_t)(k0 + (lane & 15)) * 128u
                                          + (uint32_t)(ncol + nn * 16 + (lane >> 4) * 8) * 2u);
                    ldm_x4_t(bh[nn], wbase + g * 16384 + off);
                }
                #pragma unroll
                for (int n = 0; n < 4; n++)
                    mma_f16(C[g][n], ah, &bh[n >> 1][(n & 1) * 2]);
            }
        }

        // ---- epilogue: gates -> smem a/nx tiles ----
        #pragma unroll
        for (int hf = 0; hf < 2; hf++) {
            const int rloc = mrow + (lane >> 2) + hf * 8;
            const bool rst = (((row0 + it * 64 + rloc) & (T_ - 1)) == 0);
            #pragma unroll
            for (int n = 0; n < 4; n++) {
                const int col = ncol + n * 8 + (lane & 3) * 2;   // local [0,64)
                float v1a = C[0][n][hf * 2], v1b = C[0][n][hf * 2 + 1];
                float v2a = C[1][n][hf * 2], v2b = C[1][n][hf * 2 + 1];
                uint32_t xoff = swz256((uint32_t)rloc * 256u
                                       + (uint32_t)(half * 64 + col) * 2u);
                __half2 xhp = *(__half2*)(sm + SM_XH + xoff);
                float x0 = __half2float(xhp.x);
                float x1 = __half2float(xhp.y);
                float gx0 = sigm(v1a + b1v[col]),     gx1 = sigm(v1b + b1v[col + 1]);
                float ga0 = sigm(v2a + b2v[col]),     ga1 = sigm(v2b + b2v[col + 1]);
                float a0 = __expf(-scv[col] * ga0);
                float a1 = __expf(-scv[col + 1] * ga1);
                float m0 = sqrt_ap(fmaxf(0.f, 1.f - a0 * a0));
                float m1 = sqrt_ap(fmaxf(0.f, 1.f - a1 * a1));
                if (rst) { a0 = 0.f; a1 = 0.f; m0 = 1.f; m1 = 1.f; }
                float2 av; av.x = a0; av.y = a1;
                float2 nv; nv.x = x0 * gx0 * m0; nv.y = x1 * gx1 * m1;
                *(float2*)&sA [rloc * SP + col] = av;
                *(float2*)&sNX[rloc * SP + col] = nv;
            }
        }
        __syncthreads();

        // ---- phase 1: 8-step register scan (warp = seg, lane = chan pair) ----
        float2 yl[8], pl[8];
        float2 hv; hv.x = 0.f; hv.y = 0.f;
        float2 pv; pv.x = 1.f; pv.y = 1.f;
        const int t0 = seg * 8;
        #pragma unroll
        for (int t = 0; t < 8; t++) {
            float2 a  = *(float2*)&sA [(t0 + t) * SP + cp];
            float2 nx = *(float2*)&sNX[(t0 + t) * SP + cp];
            hv.x = fmaf(a.x, hv.x, nx.x); hv.y = fmaf(a.y, hv.y, nx.y);
            pv.x *= a.x;                  pv.y *= a.y;
            yl[t] = hv; pl[t] = pv;
        }
        *(float2*)&sgA[seg * 64 + cp] = pv;
        *(float2*)&sgH[seg * 64 + cp] = hv;
        __syncthreads();

        // ---- phase 2+3: fold inbound carry, fix + store to gmem ----
        float2 cih = *(float2*)&hrun[p * 64 + cp];
        float2 cip = *(float2*)&prun[p * 64 + cp];
        for (int s = 0; s < seg; s++) {
            float2 A  = *(float2*)&sgA[s * 64 + cp];
            float2 Hh = *(float2*)&sgH[s * 64 + cp];
            cih.x = fmaf(A.x, cih.x, Hh.x); cih.y = fmaf(A.y, cih.y, Hh.y);
            cip.x *= A.x;                   cip.y *= A.y;
        }
        if (seg == 7) {
            float2 nh, np;
            nh.x = fmaf(pv.x, cih.x, hv.x); nh.y = fmaf(pv.y, cih.y, hv.y);
            np.x = cip.x * pv.x;            np.y = cip.y * pv.y;
            *(float2*)&hrun[(p ^ 1) * 64 + cp] = nh;
            *(float2*)&prun[(p ^ 1) * 64 + cp] = np;
        }
        {
            const size_t gtile = (size_t)(row0 + it * 64 + t0) * W_ + col0 + cp;
            #pragma unroll
            for (int t = 0; t < 8; t++) {
                float2 yv;
                yv.x = fmaf(pl[t].x, cih.x, yl[t].x);
                yv.y = fmaf(pl[t].y, cih.y, yl[t].y);
                *(float2*)&y[gtile + (size_t)t * W_] = yv;
                if (c != 0) {
                    __half2 Pv;
                    Pv.x = __float2half_rn(pl[t].x * cip.x);
                    Pv.y = __float2half_rn(pl[t].y * cip.y);
                    *(__half2*)&g_Ph[gtile + (size_t)t * W_] = Pv;
                }
            }
        }
    }

    __syncthreads();
    if (tid < 32) {   // final carries live in parity 0 (after 8 iters)
        int sidx = bx * W_ + col0 + cp;
        *(float2*)&g_hlast[sidx] = *(float2*)&hrun[cp];
        *(float2*)&g_Aprod[sidx] = *(float2*)&prun[cp];
    }
}

// ---------------- kernel 2: apply carries (inline carry chain) ----------------
__global__ void __launch_bounds__(1024) apply_kernel(float* __restrict__ y)
{
    const int sub  = blockIdx.x & 7;
    const int c    = (blockIdx.x >> 3) + 1;     // 1..7
    const int b    = blockIdx.y;
    const int pid  = threadIdx.x & 511;         // channel pair
    const int rpar = threadIdx.x >> 9;          // row parity
    const int ch   = pid * 2;

    float2 carry; carry.x = 0.f; carry.y = 0.f;
    for (int s = 0; s < c; s++) {
        int sidx = (b * NCH + s) * W_ + ch;
        float2 A  = *(const float2*)&g_Aprod[sidx];
        float2 Hh = *(const float2*)&g_hlast[sidx];
        carry.x = fmaf(A.x, carry.x, Hh.x);
        carry.y = fmaf(A.y, carry.y, Hh.y);
    }

    size_t base = ((size_t)b * T_ + (size_t)c * 512 + (size_t)sub * 64 + rpar) * W_ + ch;
    #pragma unroll 8
    for (int t = 0; t < 32; t++) {
        size_t idx = base + (size_t)t * 2 * W_;
        __half2 Ph = *(const __half2*)&g_Ph[idx];
        float2 yv = *(float2*)&y[idx];
        yv.x = fmaf(__half2float(Ph.x), carry.x, yv.x);
        yv.y = fmaf(__half2float(Ph.y), carry.y, yv.y);
        *(float2*)&y[idx] = yv;
    }
}

// ---------------------------------------------------------------------------
extern "C" void kernel_launch(void* const* d_in, const int* in_sizes, int n_in,
                              void* d_out, int out_size)
{
    const float* x       = (const float*)d_in[0];
    const float* w_in    = (const float*)d_in[1];
    const float* b_in    = (const float*)d_in[2];
    const float* w_a     = (const float*)d_in[3];
    const float* b_a     = (const float*)d_in[4];
    const float* a_param = (const float*)d_in[5];
    float* y = (float*)d_out;

    cudaFuncSetAttribute(gates_kernel,
                         cudaFuncAttributeMaxDynamicSharedMemorySize, SM_TOTAL);

    wprep_kernel<<<dim3(H_, 2), 256>>>(w_in, w_a);
    gates_kernel<<<dim3(B_ * NCH, H_ * 2), 256, SM_TOTAL>>>(x, b_in, b_a, a_param, y);
    apply_kernel<<<dim3(56, B_), 1024>>>(y);
}

// round 12
// speedup vs baseline: 1.5941x; 1.0417x over previous
#include <cuda_runtime.h>
#include <cuda_fp16.h>
#include <cstdint>
#include <math.h>

#define B_   8
#define T_   4096
#define W_   1024
#define H_   8
#define NCH  4      // chunks per batch (1024 steps each)
#define CHL  1024   // chunk length
#define ITERS 16    // 64-step tiles per chunk

// ---------------- scratch ----------------
__device__ __half g_Ph [(size_t)B_ * T_ * W_];   // chunk prefix products (fp16)
__device__ __half g_Ylh[(size_t)B_ * T_ * W_];   // chunk-local y (fp16, c>0 only)
__device__ float  g_Aprod[B_ * NCH * W_];
__device__ float  g_hlast[B_ * NCH * W_];

// ---------------- smem layout (bytes) ----------------
#define SP        66                        // scan tile row stride (floats)
#define SM_W      0                         // 2 x 16384 (fp16 w1,w2 half-cols)
#define SM_XH     32768                     // 16384 (64 rows x 128 k fp16)
#define SM_SA     49152                     // 64*66*4 = 16896
#define SM_SNX    66048                     // 16896
#define SM_SC     82944                     // 256
#define SM_B1     83200
#define SM_B2     83456
#define SM_SEGA   83712                     // 8*64*4 = 2048
#define SM_SEGH   85760
#define SM_HRUN   87808                     // 2*64*4 parity
#define SM_PRUN   88320
#define SM_TOTAL  88832

__device__ __forceinline__ uint32_t smem_u32(const void* p) {
    uint32_t a;
    asm("{ .reg .u64 t; cvta.to.shared.u64 t, %1; cvt.u32.u64 %0, t; }" : "=r"(a) : "l"(p));
    return a;
}
__device__ __forceinline__ uint32_t swz256(uint32_t o) {
    return o ^ (((o >> 8) & 7u) << 4);
}
__device__ __forceinline__ uint32_t swz128(uint32_t o) {
    return o ^ ((o >> 3) & 0x70u);
}
__device__ __forceinline__ void ldm_x4(uint32_t* r, uint32_t addr) {
    asm volatile("ldmatrix.sync.aligned.m8n8.x4.shared.b16 {%0,%1,%2,%3}, [%4];"
        : "=r"(r[0]), "=r"(r[1]), "=r"(r[2]), "=r"(r[3]) : "r"(addr));
}
__device__ __forceinline__ void ldm_x4_t(uint32_t* r, uint32_t addr) {
    asm volatile("ldmatrix.sync.aligned.m8n8.x4.trans.shared.b16 {%0,%1,%2,%3}, [%4];"
        : "=r"(r[0]), "=r"(r[1]), "=r"(r[2]), "=r"(r[3]) : "r"(addr));
}
__device__ __forceinline__ void mma_f16(float* c, const uint32_t* a, const uint32_t* b) {
    asm volatile("mma.sync.aligned.m16n8k16.row.col.f32.f16.f16.f32 "
        "{%0,%1,%2,%3}, {%4,%5,%6,%7}, {%8,%9}, {%0,%1,%2,%3};"
        : "+f"(c[0]), "+f"(c[1]), "+f"(c[2]), "+f"(c[3])
        : "r"(a[0]), "r"(a[1]), "r"(a[2]), "r"(a[3]), "r"(b[0]), "r"(b[1]));
}
__device__ __forceinline__ float sigm(float v) {
    float t;
    asm("tanh.approx.f32 %0, %1;" : "=f"(t) : "f"(v * 0.5f));
    return fmaf(0.5f, t, 0.5f);
}
__device__ __forceinline__ float sqrt_ap(float v) {
    float r; asm("sqrt.approx.f32 %0, %1;" : "=f"(r) : "f"(v)); return r;
}
__device__ __forceinline__ uint32_t packh2(float a, float b) {
    __half2 t; t.x = __float2half_rn(a); t.y = __float2half_rn(b);
    return *(uint32_t*)&t;
}

// ---------------------------------------------------------------------------
// kernel 1: gates GEMM + fused scan. block = (chunk, head-half). 256 threads.
// 2 CTAs/SM. Weights converted inline from fp32 (L2-shared).
// ---------------------------------------------------------------------------
__global__ void __launch_bounds__(256, 2) gates_kernel(
    const float* __restrict__ x, const float* __restrict__ w_in,
    const float* __restrict__ b_in, const float* __restrict__ w_a,
    const float* __restrict__ b_a, const float* __restrict__ a_param,
    float* __restrict__ y)
{
    extern __shared__ char sm[];
    const int tid = threadIdx.x, wid = tid >> 5, lane = tid & 31;
    const int h = blockIdx.y >> 1, half = blockIdx.y & 1;
    const int bx = blockIdx.x;                 // b*NCH + chunk
    const int c  = bx & (NCH - 1);
    const int row0 = bx * CHL;
    const int col0 = h * 128 + half * 64;      // global channel base

    float* scv  = (float*)(sm + SM_SC);
    float* b1v  = (float*)(sm + SM_B1);
    float* b2v  = (float*)(sm + SM_B2);
    float* sA   = (float*)(sm + SM_SA);
    float* sNX  = (float*)(sm + SM_SNX);
    float* sgA  = (float*)(sm + SM_SEGA);
    float* sgH  = (float*)(sm + SM_SEGH);
    float* hrun = (float*)(sm + SM_HRUN);
    float* prun = (float*)(sm + SM_PRUN);

    // inline weight conversion: fp32 [128k x 64n slice] -> fp16 swizzled smem
    #pragma unroll
    for (int g = 0; g < 2; g++) {
        const float* wsrc = (g ? w_a : w_in) + h * 16384 + half * 64;
        char* WH = sm + SM_W + g * 16384;
        for (int idx = tid; idx < 2048; idx += 256) {
            int k = idx >> 4, n4 = (idx & 15) * 4;
            float4 v = *(const float4*)&wsrc[k * 128 + n4];
            uint32_t off = swz128((uint32_t)k * 128u + (uint32_t)n4 * 2u);
            uint2 hp;
            hp.x = packh2(v.x, v.y); hp.y = packh2(v.z, v.w);
            *(uint2*)(WH + off) = hp;
        }
    }
    if (tid < 64) {
        int ch = col0 + tid;
        scv[tid] = 8.f * log1pf(expf(a_param[ch]));
        b1v[tid] = b_in[ch];
        b2v[tid] = b_a[ch];
    }
    if (tid < 32) {
        float2 z; z.x = 0.f; z.y = 0.f;
        float2 o; o.x = 1.f; o.y = 1.f;
        *(float2*)&hrun[tid * 2] = z;
        *(float2*)&prun[tid * 2] = o;
    }

    const int pr = tid >> 5, pc4 = (tid & 31) * 4;
    float4 xr[8];
    #pragma unroll
    for (int i = 0; i < 8; i++)
        xr[i] = *(const float4*)&x[(size_t)(row0 + pr + i * 8) * W_ + h * 128 + pc4];
    __syncthreads();

    const uint32_t xh_b  = smem_u32(sm + SM_XH);
    const uint32_t wbase = smem_u32(sm + SM_W);

    const int cw = wid >> 2, rw = wid & 3;
    const int mrow = rw * 16, ncol = cw * 32;
    const int cp  = lane * 2;
    const int seg = wid;

    for (int it = 0; it < ITERS; it++) {
        const int p = it & 1;
        // ---- stage x -> smem fp16 (swizzled 256B rows) ----
        #pragma unroll
        for (int i = 0; i < 8; i++) {
            float4 v = xr[i];
            uint32_t off = swz256((uint32_t)(pr + i * 8) * 256u + (uint32_t)pc4 * 2u);
            uint2 hp;
            hp.x = packh2(v.x, v.y); hp.y = packh2(v.z, v.w);
            *(uint2*)(sm + SM_XH + off) = hp;
        }
        __syncthreads();

        if (it < ITERS - 1) {
            #pragma unroll
            for (int i = 0; i < 8; i++)
                xr[i] = *(const float4*)&x[(size_t)(row0 + (it + 1) * 64 + pr + i * 8) * W_ + h * 128 + pc4];
        }

        // ---- mma: single-pass fp16, both gemms, warp tile 16x32 ----
        float C[2][4][4];
        #pragma unroll
        for (int g = 0; g < 2; g++)
            #pragma unroll
            for (int n = 0; n < 4; n++)
                #pragma unroll
                for (int e = 0; e < 4; e++) C[g][n][e] = 0.f;

        #pragma unroll
        for (int kt = 0; kt < 8; kt++) {
            const int k0 = kt * 16;
            uint32_t ah[4];
            {
                uint32_t off = swz256((uint32_t)(mrow + (lane & 15)) * 256u
                                      + (uint32_t)(k0 + (lane >> 4) * 8) * 2u);
                ldm_x4(ah, xh_b + off);
            }
            #pragma unroll
            for (int g = 0; g < 2; g++) {
                uint32_t bh[2][4];
                #pragma unroll
                for (int nn = 0; nn < 2; nn++) {
                    uint32_t off = swz128((uint32_t)(k0 + (lane & 15)) * 128u
                                          + (uint32_t)(ncol + nn * 16 + (lane >> 4) * 8) * 2u);
                    ldm_x4_t(bh[nn], wbase + g * 16384 + off);
                }
                #pragma unroll
                for (int n = 0; n < 4; n++)
                    mma_f16(C[g][n], ah, &bh[n >> 1][(n & 1) * 2]);
            }
        }

        // ---- epilogue: gates -> smem a/nx tiles ----
        #pragma unroll
        for (int hf = 0; hf < 2; hf++) {
            const int rloc = mrow + (lane >> 2) + hf * 8;
            const bool rst = (((row0 + it * 64 + rloc) & (T_ - 1)) == 0);
            #pragma unroll
            for (int n = 0; n < 4; n++) {
                const int col = ncol + n * 8 + (lane & 3) * 2;
                float v1a = C[0][n][hf * 2], v1b = C[0][n][hf * 2 + 1];
                float v2a = C[1][n][hf * 2], v2b = C[1][n][hf * 2 + 1];
                uint32_t xoff = swz256((uint32_t)rloc * 256u
                                       + (uint32_t)(half * 64 + col) * 2u);
                __half2 xhp = *(__half2*)(sm + SM_XH + xoff);
                float x0 = __half2float(xhp.x);
                float x1 = __half2float(xhp.y);
                float gx0 = sigm(v1a + b1v[col]),     gx1 = sigm(v1b + b1v[col + 1]);
                float ga0 = sigm(v2a + b2v[col]),     ga1 = sigm(v2b + b2v[col + 1]);
                float a0 = __expf(-scv[col] * ga0);
                float a1 = __expf(-scv[col + 1] * ga1);
                float m0 = sqrt_ap(fmaxf(0.f, 1.f - a0 * a0));
                float m1 = sqrt_ap(fmaxf(0.f, 1.f - a1 * a1));
                if (rst) { a0 = 0.f; a1 = 0.f; m0 = 1.f; m1 = 1.f; }
                float2 av; av.x = a0; av.y = a1;
                float2 nv; nv.x = x0 * gx0 * m0; nv.y = x1 * gx1 * m1;
                *(float2*)&sA [rloc * SP + col] = av;
                *(float2*)&sNX[rloc * SP + col] = nv;
            }
        }
        __syncthreads();

        // ---- phase 1: 8-step register scan (warp = seg, lane = chan pair) ----
        float2 yl[8], pl[8];
        float2 hv; hv.x = 0.f; hv.y = 0.f;
        float2 pv; pv.x = 1.f; pv.y = 1.f;
        const int t0 = seg * 8;
        #pragma unroll
        for (int t = 0; t < 8; t++) {
            float2 a  = *(float2*)&sA [(t0 + t) * SP + cp];
            float2 nx = *(float2*)&sNX[(t0 + t) * SP + cp];
            hv.x = fmaf(a.x, hv.x, nx.x); hv.y = fmaf(a.y, hv.y, nx.y);
            pv.x *= a.x;                  pv.y *= a.y;
            yl[t] = hv; pl[t] = pv;
        }
        *(float2*)&sgA[seg * 64 + cp] = pv;
        *(float2*)&sgH[seg * 64 + cp] = hv;
        __syncthreads();

        // ---- phase 2+3: fold inbound carry, fix + store to gmem ----
        float2 cih = *(float2*)&hrun[p * 64 + cp];
        float2 cip = *(float2*)&prun[p * 64 + cp];
        for (int s = 0; s < seg; s++) {
            float2 A  = *(float2*)&sgA[s * 64 + cp];
            float2 Hh = *(float2*)&sgH[s * 64 + cp];
            cih.x = fmaf(A.x, cih.x, Hh.x); cih.y = fmaf(A.y, cih.y, Hh.y);
            cip.x *= A.x;                   cip.y *= A.y;
        }
        if (seg == 7) {
            float2 nh, np;
            nh.x = fmaf(pv.x, cih.x, hv.x); nh.y = fmaf(pv.y, cih.y, hv.y);
            np.x = cip.x * pv.x;            np.y = cip.y * pv.y;
            *(float2*)&hrun[(p ^ 1) * 64 + cp] = nh;
            *(float2*)&prun[(p ^ 1) * 64 + cp] = np;
        }
        {
            const size_t gtile = (size_t)(row0 + it * 64 + t0) * W_ + col0 + cp;
            if (c == 0) {
                #pragma unroll
                for (int t = 0; t < 8; t++) {
                    float2 yv;
                    yv.x = fmaf(pl[t].x, cih.x, yl[t].x);
                    yv.y = fmaf(pl[t].y, cih.y, yl[t].y);
                    *(float2*)&y[gtile + (size_t)t * W_] = yv;
                }
            } else {
                #pragma unroll
                for (int t = 0; t < 8; t++) {
                    __half2 Yv, Pv;
                    Yv.x = __float2half_rn(fmaf(pl[t].x, cih.x, yl[t].x));
                    Yv.y = __float2half_rn(fmaf(pl[t].y, cih.y, yl[t].y));
                    Pv.x = __float2half_rn(pl[t].x * cip.x);
                    Pv.y = __float2half_rn(pl[t].y * cip.y);
                    *(__half2*)&g_Ylh[gtile + (size_t)t * W_] = Yv;
                    *(__half2*)&g_Ph [gtile + (size_t)t * W_] = Pv;
                }
            }
        }
    }

    __syncthreads();
    if (tid < 32) {   // final carries live in parity 0 (ITERS even)
        int sidx = bx * W_ + col0 + cp;
        *(float2*)&g_hlast[sidx] = *(float2*)&hrun[cp];
        *(float2*)&g_Aprod[sidx] = *(float2*)&prun[cp];
    }
}

// ---------------- kernel 2: apply carries, write final fp32 y ----------------
__global__ void __launch_bounds__(1024) apply_kernel(float* __restrict__ y)
{
    const int sub  = blockIdx.x & 15;
    const int c    = (blockIdx.x >> 4) + 1;     // 1..3
    const int b    = blockIdx.y;
    const int pid  = threadIdx.x & 511;         // channel pair
    const int rpar = threadIdx.x >> 9;          // row parity
    const int ch   = pid * 2;

    float2 carry; carry.x = 0.f; carry.y = 0.f;
    for (int s = 0; s < c; s++) {
        int sidx = (b * NCH + s) * W_ + ch;
        float2 A  = *(const float2*)&g_Aprod[sidx];
        float2 Hh = *(const float2*)&g_hlast[sidx];
        carry.x = fmaf(A.x, carry.x, Hh.x);
        carry.y = fmaf(A.y, carry.y, Hh.y);
    }

    size_t base = ((size_t)b * T_ + (size_t)c * CHL + (size_t)sub * 64 + rpar) * W_ + ch;
    #pragma unroll 8
    for (int t = 0; t < 32; t++) {
        size_t idx = base + (size_t)t * 2 * W_;
        __half2 Yl = *(const __half2*)&g_Ylh[idx];
        __half2 Ph = *(const __half2*)&g_Ph [idx];
        float2 yv;
        yv.x = fmaf(__half2float(Ph.x), carry.x, __half2float(Yl.x));
        yv.y = fmaf(__half2float(Ph.y), carry.y, __half2float(Yl.y));
        *(float2*)&y[idx] = yv;
    }
}

// ---------------------------------------------------------------------------
extern "C" void kernel_launch(void* const* d_in, const int* in_sizes, int n_in,
                              void* d_out, int out_size)
{
    const float* x       = (const float*)d_in[0];
    const float* w_in    = (const float*)d_in[1];
    const float* b_in    = (const float*)d_in[2];
    const float* w_a     = (const float*)d_in[3];
    const float* b_a     = (const float*)d_in[4];
    const float* a_param = (const float*)d_in[5];
    float* y = (float*)d_out;

    cudaFuncSetAttribute(gates_kernel,
                         cudaFuncAttributeMaxDynamicSharedMemorySize, SM_TOTAL);

    gates_kernel<<<dim3(B_ * NCH, H_ * 2), 256, SM_TOTAL>>>(x, w_in, b_in, w_a, b_a, a_param, y);
    apply_kernel<<<dim3((NCH - 1) * 16, B_), 1024>>>(y);
}